// round 2
// baseline (speedup 1.0000x reference)
#include <cuda_runtime.h>
#include <cstdint>

// Problem constants (fixed by setup_inputs)
#define E_MAX   1600000
#define HEADS   8
#define NNODES  50000

// Scratch (static __device__ — no allocations allowed)
__device__ float g_ex[E_MAX * HEADS];        // exp(pre) per (edge, head)   51.2 MB
__device__ float g_segsum[NNODES * HEADS];   // per-(node, head) sums        1.6 MB
__device__ int   g_idx32[E_MAX];             // index converted to int32     6.4 MB
__device__ int   g_is64;                     // dtype flag for index input

// ---------------------------------------------------------------------------
// Detect whether the index buffer is int64 or int32.
// int64 little-endian positive values => every odd int32 word is 0.
// int32 sorted node ids in [0,50000) => odd words are (almost surely) nonzero.
// ---------------------------------------------------------------------------
__global__ void detect_kernel(const int* __restrict__ idx_raw, int E)
{
    __shared__ int any_nonzero;
    if (threadIdx.x == 0) any_nonzero = 0;
    __syncthreads();
    int pos = 2 * threadIdx.x + 1;          // odd int32 positions 1..255
    if (pos < E) {                          // int32 view has >= E elements either way
        if (idx_raw[pos] != 0) any_nonzero = 1;   // benign race
    }
    __syncthreads();
    if (threadIdx.x == 0) g_is64 = (any_nonzero == 0) ? 1 : 0;
}

__global__ void convert_kernel(const void* __restrict__ idx_raw, int E)
{
    int e = blockIdx.x * blockDim.x + threadIdx.x;
    if (e >= E) return;
    if (g_is64)
        g_idx32[e] = (int)((const long long*)idx_raw)[e];
    else
        g_idx32[e] = ((const int*)idx_raw)[e];
}

__global__ void zero_kernel()
{
    int i = blockIdx.x * blockDim.x + threadIdx.x;
    if (i < NNODES * HEADS) g_segsum[i] = 0.0f;
}

// ---------------------------------------------------------------------------
// K1: warp-per-edge dot product, exp, store ex, atomic segment-sum.
// Per edge: q and k are each 128 contiguous floats laid out [m(2), h(8), c(8)].
// Lane l loads float4 at offset 4l -> belongs to (m = l/16, h = (l%16)/2).
// shfl_xor(1) merges the two lanes of an h; shfl_xor(16) merges m=0 with m=1.
// After both, lanes {2h, 2h+1, 2h+16, 2h+17} all hold pre[h].
// ---------------------------------------------------------------------------
__global__ void dot_kernel(const float4* __restrict__ q,
                           const float4* __restrict__ k,
                           int E)
{
    int gtid = blockIdx.x * blockDim.x + threadIdx.x;
    int edge = gtid >> 5;
    int lane = threadIdx.x & 31;
    if (edge >= E) return;

    long base = (long)edge * 32 + lane;
    float4 a = q[base];
    float4 b = k[base];
    float r = a.x * b.x + a.y * b.y + a.z * b.z + a.w * b.w;

    r += __shfl_xor_sync(0xffffffffu, r, 1);
    r += __shfl_xor_sync(0xffffffffu, r, 16);

    if (lane < 16 && !(lane & 1)) {
        int h = lane >> 1;
        // scale = C^-0.5 = 8^-0.5
        float ex = expf(r * 0.35355339059327373f);
        g_ex[(long)edge * HEADS + h] = ex;
        int node = g_idx32[edge];
        atomicAdd(&g_segsum[node * HEADS + h], ex);
    }
}

// ---------------------------------------------------------------------------
// K2: normalize. out[e,h] = ex[e,h] / (segsum[idx[e],h] + 1e-16)
// ---------------------------------------------------------------------------
__global__ void norm_kernel(float* __restrict__ out, int E)
{
    int i = blockIdx.x * blockDim.x + threadIdx.x;
    if (i >= E * HEADS) return;
    int e = i >> 3;
    int h = i & 7;
    int node = g_idx32[e];
    out[i] = g_ex[i] / (g_segsum[node * HEADS + h] + 1e-16f);
}

extern "C" void kernel_launch(void* const* d_in, const int* in_sizes, int n_in,
                              void* d_out, int out_size)
{
    const float4* q = (const float4*)d_in[0];
    const float4* k = (const float4*)d_in[1];
    const void* idx = d_in[2];

    int E = in_sizes[0] / 128;   // q is [E, 2, 8, 8] fp32

    detect_kernel<<<1, 128>>>((const int*)idx, E);
    convert_kernel<<<(E + 255) / 256, 256>>>(idx, E);
    zero_kernel<<<(NNODES * HEADS + 255) / 256, 256>>>();

    // warp per edge => E*32 threads
    long nthreads = (long)E * 32;
    int blocks = (int)((nthreads + 255) / 256);
    dot_kernel<<<blocks, 256>>>(q, k, E);

    norm_kernel<<<(E * HEADS + 255) / 256, 256>>>((float*)d_out, E);
}

// round 5
// speedup vs baseline: 1.2645x; 1.2645x over previous
#include <cuda_runtime.h>
#include <cstdint>

#define E_MAX   1600000
#define HEADS   8
#define NNODES  50000

__device__ float g_segsum[NNODES * HEADS];   // sums, then reciprocals (in place)
__device__ int   g_is64;                     // index dtype flag

// ---------------------------------------------------------------------------
// setup: zero seg_sum; block 0 also sniffs the index dtype.
// int64 little-endian values < 50000 => every odd int32 word is 0.
// ---------------------------------------------------------------------------
__global__ void setup_kernel(const int* __restrict__ idx_raw)
{
    int i = blockIdx.x * blockDim.x + threadIdx.x;
    if (i < NNODES * HEADS) g_segsum[i] = 0.0f;

    if (blockIdx.x == 0) {
        __shared__ int nz;
        if (threadIdx.x == 0) nz = 0;
        __syncthreads();
        int pos = 2 * threadIdx.x + 1;      // odd words 1..255 (E >> 256 both ways)
        if (pos < 256 && idx_raw[pos] != 0) nz = 1;   // benign race
        __syncthreads();
        if (threadIdx.x == 0) g_is64 = (nz == 0) ? 1 : 0;
    }
}

// ---------------------------------------------------------------------------
// K1: each warp handles 4 consecutive edges.
// q/k layout per edge: 128 contiguous floats [m(2), h(8), c(8)].
// Lane l loads float4 at offset 4l -> (m = l/16, h = (l%16)/2).
// shfl_xor(1) merges c-halves of an h; shfl_xor(16) merges m=0,m=1.
// After both, every lane holds pre[h=(lane&15)>>1].
// ex is written (coalesced 128B per warp) into d_out; normalized in place later.
// Atomics deduped across the 4 edges (index is sorted -> usually same node).
// ---------------------------------------------------------------------------
__global__ void __launch_bounds__(256)
dot_kernel(const float4* __restrict__ q,
           const float4* __restrict__ k,
           const void*  __restrict__ idx_raw,
           float* __restrict__ ex_out,
           int E)
{
    int warp = (blockIdx.x * blockDim.x + threadIdx.x) >> 5;
    int lane = threadIdx.x & 31;
    int e0   = warp * 4;
    if (e0 >= E) return;

    // node ids for the 4 edges (broadcast loads)
    int node[4];
    if (g_is64) {
        const long long* p = (const long long*)idx_raw;
        #pragma unroll
        for (int i = 0; i < 4; i++) node[i] = (int)p[e0 + i];
    } else {
        const int* p = (const int*)idx_raw;
        #pragma unroll
        for (int i = 0; i < 4; i++) node[i] = p[e0 + i];
    }

    // 8 independent 16B loads in flight
    float4 a[4], b[4];
    #pragma unroll
    for (int i = 0; i < 4; i++) {
        long base = (long)(e0 + i) * 32 + lane;
        a[i] = q[base];
        b[i] = k[base];
    }

    float ex[4];
    #pragma unroll
    for (int i = 0; i < 4; i++) {
        float r = a[i].x * b[i].x + a[i].y * b[i].y
                + a[i].z * b[i].z + a[i].w * b[i].w;
        r += __shfl_xor_sync(0xffffffffu, r, 1);
        r += __shfl_xor_sync(0xffffffffu, r, 16);
        ex[i] = __expf(r * 0.35355339059327373f);   // * C^-0.5
    }

    // Coalesced store: dest lane d wants (edge i=d>>3, head h=d&7),
    // whose value lives at source lane 2h.
    {
        int src = (lane & 7) * 2;
        float t0 = __shfl_sync(0xffffffffu, ex[0], src);
        float t1 = __shfl_sync(0xffffffffu, ex[1], src);
        float t2 = __shfl_sync(0xffffffffu, ex[2], src);
        float t3 = __shfl_sync(0xffffffffu, ex[3], src);
        float v = (lane < 8) ? t0 : (lane < 16) ? t1 : (lane < 24) ? t2 : t3;
        ex_out[(long)e0 * HEADS + lane] = v;
    }

    // Segment-sum atomics, deduped over the 4 (sorted) edges.
    if (lane < 16 && !(lane & 1)) {
        int h = lane >> 1;
        float acc = ex[0];
        int cur = node[0];
        #pragma unroll
        for (int i = 1; i < 4; i++) {
            if (node[i] == cur) {
                acc += ex[i];
            } else {
                atomicAdd(&g_segsum[cur * HEADS + h], acc);
                cur = node[i];
                acc = ex[i];
            }
        }
        atomicAdd(&g_segsum[cur * HEADS + h], acc);
    }
}

// ---------------------------------------------------------------------------
// rcp: seg_sum -> 1/(seg_sum + 1e-16), in place (400k elements, trivial)
// ---------------------------------------------------------------------------
__global__ void rcp_kernel()
{
    int i = blockIdx.x * blockDim.x + threadIdx.x;
    if (i < NNODES * HEADS) g_segsum[i] = 1.0f / (g_segsum[i] + 1e-16f);
}

// ---------------------------------------------------------------------------
// norm: thread per edge; float4 x2 in-place on d_out; multiply by reciprocal.
// ---------------------------------------------------------------------------
__global__ void __launch_bounds__(256)
norm_kernel(float4* __restrict__ out, const void* __restrict__ idx_raw, int E)
{
    int e = blockIdx.x * blockDim.x + threadIdx.x;
    if (e >= E) return;

    int node = g_is64 ? (int)((const long long*)idx_raw)[e]
                      : ((const int*)idx_raw)[e];

    const float4* s = (const float4*)&g_segsum[node * HEADS];
    float4 s0 = s[0], s1 = s[1];

    float4 x0 = out[(long)e * 2];
    float4 x1 = out[(long)e * 2 + 1];
    x0.x *= s0.x; x0.y *= s0.y; x0.z *= s0.z; x0.w *= s0.w;
    x1.x *= s1.x; x1.y *= s1.y; x1.z *= s1.z; x1.w *= s1.w;
    out[(long)e * 2]     = x0;
    out[(long)e * 2 + 1] = x1;
}

extern "C" void kernel_launch(void* const* d_in, const int* in_sizes, int n_in,
                              void* d_out, int out_size)
{
    const float4* q = (const float4*)d_in[0];
    const float4* k = (const float4*)d_in[1];
    const void*   idx = d_in[2];

    int E = in_sizes[0] / 128;   // q is [E, 2, 8, 8] fp32

    setup_kernel<<<(NNODES * HEADS + 255) / 256, 256>>>((const int*)idx);

    // warp per 4 edges => E/4 warps => E*8 threads
    long nthreads = (long)E * 8;
    dot_kernel<<<(int)((nthreads + 255) / 256), 256>>>(q, k, idx,
                                                       (float*)d_out, E);

    rcp_kernel<<<(NNODES * HEADS + 255) / 256, 256>>>();

    norm_kernel<<<(E + 255) / 256, 256>>>((float4*)d_out, idx, E);
}